// round 3
// baseline (speedup 1.0000x reference)
#include <cuda_runtime.h>
#include <cuda_bf16.h>

// Cost volume: out[b,h,w,(9i+jj)%81] = (1/H) * sum_c x1[b,h,w,c] * x2[b,h-i,w-jj,c]
// B=8, H=W=C=128, sr=4, D=9, OC=81. Zero padding outside.
//
// Block = (b, band of 4 output rows). 256 threads = 128 w-lanes x 2 slot-halves.
// 4 channel chunks of 32 (SMEM 111.7KB -> 2 blocks/SM, occ 25%); inner loop over the
// 12 x2 rows the band needs; each staged x2 row feeds up to 4 output rows.
// Slot s reads Bs[w+s] = x2[r][w+s-4]  =>  jj = 4 - s (mirror fixed in write-out).

#define Bb   8
#define Hh   128
#define Ww   128
#define Cc   128
#define OC   81
#define RROWS 4
#define CCH  32          // channels per chunk
#define NCC  4           // chunks
#define CPAD 36          // 36 mod 32 = 4 -> conflict-free float4 LDS within quarter-warp
#define WB   136         // x2 row width incl. +/-4 halo

#define AS_FLOATS (RROWS * Ww * CPAD)   // 4*128*36 = 18432
#define BS_FLOATS (WB * CPAD)           // 136*36  = 4896
#define CS_FLOATS (RROWS * Ww * 9)      // 4*128*9 = 4608
#define SMEM_FLOATS (AS_FLOATS + BS_FLOATS + CS_FLOATS)
#define SMEM_BYTES  (SMEM_FLOATS * 4)   // 111744 B -> 2 blocks/SM

// Full 4-row path (compile-time bounds, no predication) — the hot center iterations.
template<int NJ, int TOFF>
__device__ __forceinline__ void compute_full(const float* __restrict__ As,
                                             const float* __restrict__ Bs,
                                             float* __restrict__ Cs, int w) {
    float acc[RROWS][NJ];
#pragma unroll
    for (int rw = 0; rw < RROWS; rw++)
#pragma unroll
        for (int t = 0; t < NJ; t++) acc[rw][t] = 0.0f;

#pragma unroll 4
    for (int c4 = 0; c4 < CCH / 4; c4++) {
        float4 bv[NJ];
#pragma unroll
        for (int t = 0; t < NJ; t++)
            bv[t] = *reinterpret_cast<const float4*>(Bs + (w + TOFF + t) * CPAD + (c4 << 2));
        float4 av[RROWS];
#pragma unroll
        for (int rw = 0; rw < RROWS; rw++)
            av[rw] = *reinterpret_cast<const float4*>(As + (rw * Ww + w) * CPAD + (c4 << 2));
#pragma unroll
        for (int rw = 0; rw < RROWS; rw++) {
#pragma unroll
            for (int t = 0; t < NJ; t++) {
                acc[rw][t] += av[rw].x * bv[t].x;
                acc[rw][t] += av[rw].y * bv[t].y;
                acc[rw][t] += av[rw].z * bv[t].z;
                acc[rw][t] += av[rw].w * bv[t].w;
            }
        }
    }
#pragma unroll
    for (int rw = 0; rw < RROWS; rw++)
#pragma unroll
        for (int t = 0; t < NJ; t++)
            Cs[(rw * Ww + w) * 9 + TOFF + t] = acc[rw][t];
}

// Edge path: runtime row bounds (runs on the 7 cheap edge iterations only).
template<int NJ, int TOFF>
__device__ __forceinline__ void compute_part(const float* __restrict__ As,
                                             const float* __restrict__ Bs,
                                             float* __restrict__ Cs,
                                             int w, int row_lo, int row_hi) {
    float acc[RROWS][NJ];
#pragma unroll
    for (int rw = 0; rw < RROWS; rw++)
#pragma unroll
        for (int t = 0; t < NJ; t++) acc[rw][t] = 0.0f;

#pragma unroll 2
    for (int c4 = 0; c4 < CCH / 4; c4++) {
        float4 bv[NJ];
#pragma unroll
        for (int t = 0; t < NJ; t++)
            bv[t] = *reinterpret_cast<const float4*>(Bs + (w + TOFF + t) * CPAD + (c4 << 2));
        for (int rw = row_lo; rw <= row_hi; rw++) {
            float4 a = *reinterpret_cast<const float4*>(As + (rw * Ww + w) * CPAD + (c4 << 2));
#pragma unroll
            for (int t = 0; t < NJ; t++) {
                acc[rw][t] += a.x * bv[t].x;
                acc[rw][t] += a.y * bv[t].y;
                acc[rw][t] += a.z * bv[t].z;
                acc[rw][t] += a.w * bv[t].w;
            }
        }
    }
    for (int rw = row_lo; rw <= row_hi; rw++)
#pragma unroll
        for (int t = 0; t < NJ; t++)
            Cs[(rw * Ww + w) * 9 + TOFF + t] = acc[rw][t];
}

__global__ void __launch_bounds__(256, 2)
cost_volume_kernel(const float* __restrict__ x1,
                   const float* __restrict__ x2,
                   float* __restrict__ out) {
    extern __shared__ float sm[];
    float* As = sm;                         // [4][128][36]
    float* Bs = sm + AS_FLOATS;             // [136][36]
    float* Cs = sm + AS_FLOATS + BS_FLOATS; // [4][128][9]

    const int tid  = threadIdx.x;
    const int w    = tid & 127;
    const int hg   = tid >> 7;              // 0: slots 0..4, 1: slots 5..8
    const int bblk = blockIdx.x >> 5;
    const int h0   = (blockIdx.x & 31) << 2;
    const float invH = 1.0f / 128.0f;

    const float* x1b = x1 + ((size_t)(bblk * Hh + h0)) * (Ww * Cc);
    const float* x2b = x2 + ((size_t)bblk) * (Hh * Ww * Cc);
    float*       outb = out + ((size_t)(bblk * Hh + h0)) * (Ww * OC);

    for (int cc = 0; cc < NCC; cc++) {
        const int c0 = cc << 5;
        __syncthreads();  // previous chunk's consumers done before restaging As

        // Stage x1 band chunk: 4*128*8 float4s, 16 per thread, GMEM coalesced
        for (int idx = tid; idx < RROWS * Ww * (CCH / 4); idx += 256) {
            int row = idx >> 10;
            int rem = idx & 1023;
            int ww  = rem >> 3;
            int c4  = rem & 7;
            float4 v = *reinterpret_cast<const float4*>(
                x1b + (((row << 7) + ww) << 7) + c0 + (c4 << 2));
            *reinterpret_cast<float4*>(As + (row * Ww + ww) * CPAD + (c4 << 2)) = v;
        }

        for (int rr = 0; rr < 12; rr++) {
            const int r = h0 - 4 + rr;
            const bool rvalid = ((unsigned)r < (unsigned)Hh);
            const int row_lo = (rr - 8 > 0) ? rr - 8 : 0;
            const int row_hi = (rr < 3) ? rr : 3;

            __syncthreads();  // previous Bs/Cs consumers done (covers As stage at rr=0)

            if (rvalid) {
                // Stage x2 row r chunk with +/-4 halo, zero-filled at W edges
                for (int idx = tid; idx < WB * (CCH / 4); idx += 256) {
                    int wp = idx >> 3;
                    int c4 = idx & 7;
                    int w2 = wp - 4;
                    float4 v = make_float4(0.f, 0.f, 0.f, 0.f);
                    if ((unsigned)w2 < (unsigned)Ww)
                        v = *reinterpret_cast<const float4*>(
                            x2b + (((r << 7) + w2) << 7) + c0 + (c4 << 2));
                    *reinterpret_cast<float4*>(Bs + wp * CPAD + (c4 << 2)) = v;
                }
            }
            __syncthreads();

            if (rvalid) {
                if (row_lo == 0 && row_hi == 3) {
                    if (hg == 0) compute_full<5, 0>(As, Bs, Cs, w);
                    else         compute_full<4, 5>(As, Bs, Cs, w);
                } else {
                    if (hg == 0) compute_part<5, 0>(As, Bs, Cs, w, row_lo, row_hi);
                    else         compute_part<4, 5>(As, Bs, Cs, w, row_lo, row_hi);
                }
            }
            __syncthreads();

            // Write (near-coalesced) via Cs transpose buffer
            {
                const int nact  = row_hi - row_lo + 1;
                const int total = nact * Ww * 9;
                for (int idx = tid; idx < total; idx += 256) {
                    int rowl = idx / (Ww * 9);
                    int rem  = idx - rowl * (Ww * 9);
                    int ww   = rem / 9;
                    int s    = rem - ww * 9;          // slot index (0..8)
                    int row  = row_lo + rowl;
                    int ival = row + 4 - rr;          // i = h - r
                    int oc   = 9 * ival + (4 - s);    // jj = 4 - s (slot mirror)
                    if (oc < 0) oc += OC;             // torch negative-index wrap
                    float v = rvalid ? Cs[(row * Ww + ww) * 9 + s] * invH : 0.0f;
                    float* o = outb + (size_t)(row * Ww + ww) * OC + oc;
                    if (cc == 0) *o = v;
                    else         *o += v;
                }
            }
        }
    }
}

extern "C" void kernel_launch(void* const* d_in, const int* in_sizes, int n_in,
                              void* d_out, int out_size) {
    const float* x1 = (const float*)d_in[0];
    const float* x2 = (const float*)d_in[1];
    float* out = (float*)d_out;

    static bool attr_set = false;
    if (!attr_set) {
        cudaFuncSetAttribute(cost_volume_kernel,
                             cudaFuncAttributeMaxDynamicSharedMemorySize, SMEM_BYTES);
        attr_set = true;
    }

    dim3 grid(Bb * (Hh / RROWS));  // 256 blocks
    cost_volume_kernel<<<grid, 256, SMEM_BYTES>>>(x1, x2, out);
}

// round 4
// speedup vs baseline: 1.1893x; 1.1893x over previous
#include <cuda_runtime.h>
#include <cuda_bf16.h>

// Cost volume: out[b,h,w,(9i+jj)%81] = (1/H) * sum_c x1[b,h,w,c] * x2[b,h-i,w-jj,c]
// B=8, H=W=C=128, sr=4, D=9, OC=81. Zero padding outside.
//
// Block = (b, band of 4 output rows), 256 threads = 128 w-lanes x 2 slot-halves.
// Full output band Co[4][128][81] accumulated in SMEM (no GMEM RMW!), written once,
// fully coalesced (Co layout == out layout). 8 channel chunks of 16; x1 band chunk
// resident in As; 12 x2 rows staged per chunk, each feeding up to 4 output rows.
// Slot s reads Bs[w+s] = x2[r][w+s-4]  =>  jj = 4 - s (mirror handled at Co index).

#define Bb    8
#define Hh    128
#define Ww    128
#define Cc    128
#define OC    81
#define RROWS 4
#define CCH   16         // channels per chunk
#define NCC   8          // chunks
#define CPAD  20         // stride 20 floats: LDS.128 lanes cover all 32 banks, conflict-free
#define WB    136        // x2 row width incl. +/-4 halo

#define AS_FLOATS (RROWS * Ww * CPAD)   // 4*128*20 = 10240
#define BS_FLOATS (WB * CPAD)           // 136*20  = 2720
#define CO_FLOATS (RROWS * Ww * OC)     // 4*128*81 = 41472
#define SMEM_FLOATS (AS_FLOATS + BS_FLOATS + CO_FLOATS)
#define SMEM_BYTES  (SMEM_FLOATS * 4)   // 217728 B -> 1 block/SM

// Accumulate one x2 row's contribution into Co. FULL=1: all 4 rows active
// (compile-time, no predication). Co element ownership is per-thread-stable,
// so the smem RMW is race-free.
template<int NJ, int TOFF, int FULL>
__device__ __forceinline__ void compute_acc(const float* __restrict__ As,
                                            const float* __restrict__ Bs,
                                            float* __restrict__ Co,
                                            int w, int rr, int row_lo, int row_hi) {
    float acc[RROWS][NJ];
#pragma unroll
    for (int rw = 0; rw < RROWS; rw++)
#pragma unroll
        for (int t = 0; t < NJ; t++) acc[rw][t] = 0.0f;

#pragma unroll
    for (int c4 = 0; c4 < CCH / 4; c4++) {
        float4 bv[NJ];
#pragma unroll
        for (int t = 0; t < NJ; t++)
            bv[t] = *reinterpret_cast<const float4*>(Bs + (w + TOFF + t) * CPAD + (c4 << 2));
#pragma unroll
        for (int rw = 0; rw < RROWS; rw++) {
            if (FULL || (rw >= row_lo && rw <= row_hi)) {
                float4 a = *reinterpret_cast<const float4*>(As + (rw * Ww + w) * CPAD + (c4 << 2));
#pragma unroll
                for (int t = 0; t < NJ; t++) {
                    acc[rw][t] += a.x * bv[t].x;
                    acc[rw][t] += a.y * bv[t].y;
                    acc[rw][t] += a.z * bv[t].z;
                    acc[rw][t] += a.w * bv[t].w;
                }
            }
        }
    }
    // Co[row][w][oc] += acc ;  oc = 9*(row+4-rr) + (4 - s), wrapped mod 81
#pragma unroll
    for (int rw = 0; rw < RROWS; rw++) {
        if (FULL || (rw >= row_lo && rw <= row_hi)) {
            int ival = rw + 4 - rr;
#pragma unroll
            for (int t = 0; t < NJ; t++) {
                int s  = TOFF + t;
                int oc = 9 * ival + (4 - s);
                if (oc < 0) oc += OC;
                float* p = Co + (rw * Ww + w) * OC + oc;   // lane stride 81 -> conflict-free
                *p += acc[rw][t];
            }
        }
    }
}

__global__ void __launch_bounds__(256, 1)
cost_volume_kernel(const float* __restrict__ x1,
                   const float* __restrict__ x2,
                   float* __restrict__ out) {
    extern __shared__ float sm[];
    float* As = sm;                          // [4][128][20]
    float* Bs = sm + AS_FLOATS;              // [136][20]
    float* Co = sm + AS_FLOATS + BS_FLOATS;  // [4][128][81]

    const int tid  = threadIdx.x;
    const int w    = tid & 127;
    const int hg   = tid >> 7;               // 0: slots 0..4, 1: slots 5..8
    const int bblk = blockIdx.x >> 5;
    const int h0   = (blockIdx.x & 31) << 2;
    const float invH = 1.0f / 128.0f;

    const float* x1b  = x1 + ((size_t)(bblk * Hh + h0)) * (Ww * Cc);
    const float* x2b  = x2 + ((size_t)bblk) * (Hh * Ww * Cc);
    float*       outb = out + ((size_t)(bblk * Hh + h0)) * (Ww * OC);

    // Zero the output accumulator band
    for (int idx = tid; idx < CO_FLOATS; idx += 256) Co[idx] = 0.0f;

    for (int cc = 0; cc < NCC; cc++) {
        const int c0 = cc << 4;
        __syncthreads();  // previous chunk's compute done reading As (covers Co zero at cc=0)

        // Stage x1 band chunk: 4*128*4 float4s, 8 per thread, coalesced (64B per pixel-chunk)
        for (int idx = tid; idx < RROWS * Ww * (CCH / 4); idx += 256) {
            int row = idx >> 9;
            int rem = idx & 511;
            int ww  = rem >> 2;
            int c4  = rem & 3;
            float4 v = *reinterpret_cast<const float4*>(
                x1b + (((row << 7) + ww) << 7) + c0 + (c4 << 2));
            *reinterpret_cast<float4*>(As + (row * Ww + ww) * CPAD + (c4 << 2)) = v;
        }

        for (int rr = 0; rr < 12; rr++) {
            const int r = h0 - 4 + rr;
            const bool rvalid = ((unsigned)r < (unsigned)Hh);
            const int row_lo = (rr - 8 > 0) ? rr - 8 : 0;
            const int row_hi = (rr < 3) ? rr : 3;

            __syncthreads();  // previous round done reading Bs (covers As stage at rr=0)

            if (rvalid) {
                // Stage x2 row r chunk with +/-4 halo, zero-filled at W edges
                for (int idx = tid; idx < WB * (CCH / 4); idx += 256) {
                    int wp = idx >> 2;
                    int c4 = idx & 3;
                    int w2 = wp - 4;
                    float4 v = make_float4(0.f, 0.f, 0.f, 0.f);
                    if ((unsigned)w2 < (unsigned)Ww)
                        v = *reinterpret_cast<const float4*>(
                            x2b + (((r << 7) + w2) << 7) + c0 + (c4 << 2));
                    *reinterpret_cast<float4*>(Bs + wp * CPAD + (c4 << 2)) = v;
                }
            }
            __syncthreads();

            if (rvalid) {
                if (row_lo == 0 && row_hi == 3) {
                    if (hg == 0) compute_acc<5, 0, 1>(As, Bs, Co, w, rr, 0, 3);
                    else         compute_acc<4, 5, 1>(As, Bs, Co, w, rr, 0, 3);
                } else {
                    if (hg == 0) compute_acc<5, 0, 0>(As, Bs, Co, w, rr, row_lo, row_hi);
                    else         compute_acc<4, 5, 0>(As, Bs, Co, w, rr, row_lo, row_hi);
                }
            }
        }
    }

    __syncthreads();
    // Single fully-coalesced writeout: Co layout == out layout for this band
    for (int idx = tid; idx < CO_FLOATS; idx += 256)
        outb[idx] = Co[idx] * invH;
}

extern "C" void kernel_launch(void* const* d_in, const int* in_sizes, int n_in,
                              void* d_out, int out_size) {
    const float* x1 = (const float*)d_in[0];
    const float* x2 = (const float*)d_in[1];
    float* out = (float*)d_out;

    static bool attr_set = false;
    if (!attr_set) {
        cudaFuncSetAttribute(cost_volume_kernel,
                             cudaFuncAttributeMaxDynamicSharedMemorySize, SMEM_BYTES);
        attr_set = true;
    }

    dim3 grid(Bb * (Hh / RROWS));  // 256 blocks
    cost_volume_kernel<<<grid, 256, SMEM_BYTES>>>(x1, x2, out);
}

// round 5
// speedup vs baseline: 1.4551x; 1.2235x over previous
#include <cuda_runtime.h>
#include <cuda_bf16.h>

// Cost volume: out[b,h,w,(9i+jj)%81] = (1/H) * sum_c x1[b,h,w,c] * x2[b,h-i,w-jj,c]
// B=8, H=W=C=128, sr=4, D=9, OC=81. Zero padding outside.
//
// Block = (b, band of 4 output rows), 384 threads = 128 w-lanes x 3 slot-groups (3 slots each).
// Full output band Co[4][128][81] accumulated in SMEM, written once, fully coalesced.
// 8 channel chunks of 16; x1 band chunk resident in As; 12 x2 rows per chunk, DOUBLE-BUFFERED
// (prefetch row rr+1 while computing rr), one barrier per round.
// Math uses packed fma.rn.f32x2 (2 FMAs/instr) with double2 smem loads.
// Slot s reads Bs[w+s] = x2[r][w+s-4]  =>  jj = 4 - s (mirror handled at Co index).

typedef unsigned long long u64;

#define Bb    8
#define Hh    128
#define Ww    128
#define Cc    128
#define OC    81
#define RROWS 4
#define CCH   16
#define NCC   8
#define CPAD  20         // 16B-aligned rows; LDS.128 lanes cover all 32 banks (conflict-free)
#define WB    136        // x2 row width incl. +/-4 halo
#define NT    384
#define NJ    3          // slots per group

#define AS_FLOATS (RROWS * Ww * CPAD)    // 10240
#define BS_FLOATS (WB * CPAD)            // 2720 per buffer
#define CO_FLOATS (RROWS * Ww * OC)      // 41472
#define SMEM_FLOATS (AS_FLOATS + 2 * BS_FLOATS + CO_FLOATS)
#define SMEM_BYTES  (SMEM_FLOATS * 4)    // 228608 B <= 232448 max

__device__ __forceinline__ u64 fmax2(u64 a, u64 b, u64 c) {
    u64 d;
    asm("fma.rn.f32x2 %0, %1, %2, %3;" : "=l"(d) : "l"(a), "l"(b), "l"(c));
    return d;
}

__device__ __forceinline__ float hsum_x2(u64 p) {
    float lo, hi;
    asm("mov.b64 {%0, %1}, %2;" : "=f"(lo), "=f"(hi) : "l"(p));
    return lo + hi;
}

// Accumulate one x2 row's contribution into Co. FULL=1: all 4 rows active (no predication).
// Co element ownership is per-thread-stable -> smem RMW race-free.
template<int FULL>
__device__ __forceinline__ void compute_acc(const float* __restrict__ As,
                                            const float* __restrict__ Bs,
                                            float* __restrict__ Co,
                                            int w, int toff, int rr,
                                            int row_lo, int row_hi) {
    u64 acc[RROWS][NJ];
#pragma unroll
    for (int rw = 0; rw < RROWS; rw++)
#pragma unroll
        for (int t = 0; t < NJ; t++) acc[rw][t] = 0ull;

#pragma unroll
    for (int c4 = 0; c4 < CCH / 4; c4++) {
        u64 bv[NJ][2];
#pragma unroll
        for (int t = 0; t < NJ; t++) {
            double2 d = *reinterpret_cast<const double2*>(Bs + (w + toff + t) * CPAD + (c4 << 2));
            bv[t][0] = __double_as_longlong(d.x);
            bv[t][1] = __double_as_longlong(d.y);
        }
#pragma unroll
        for (int rw = 0; rw < RROWS; rw++) {
            if (FULL || (rw >= row_lo && rw <= row_hi)) {
                double2 ad = *reinterpret_cast<const double2*>(As + (rw * Ww + w) * CPAD + (c4 << 2));
                u64 a0 = __double_as_longlong(ad.x);
                u64 a1 = __double_as_longlong(ad.y);
#pragma unroll
                for (int t = 0; t < NJ; t++) {
                    acc[rw][t] = fmax2(a0, bv[t][0], acc[rw][t]);
                    acc[rw][t] = fmax2(a1, bv[t][1], acc[rw][t]);
                }
            }
        }
    }
    // Co[row][w][oc] += lo+hi ;  oc = 9*(row+4-rr) + (4 - s), wrapped mod 81
#pragma unroll
    for (int rw = 0; rw < RROWS; rw++) {
        if (FULL || (rw >= row_lo && rw <= row_hi)) {
            int ival = rw + 4 - rr;
#pragma unroll
            for (int t = 0; t < NJ; t++) {
                int s  = toff + t;
                int oc = 9 * ival + (4 - s);
                if (oc < 0) oc += OC;
                float* p = Co + (rw * Ww + w) * OC + oc;  // lane stride 81 -> conflict-free
                *p += hsum_x2(acc[rw][t]);
            }
        }
    }
}

__device__ __forceinline__ void stage_b(const float* __restrict__ x2b, float* __restrict__ Bsd,
                                        int r, int c0, int tid) {
    // Stage x2 row r chunk with +/-4 halo, zero-filled at W edges. 544 float4s.
    for (int idx = tid; idx < WB * (CCH / 4); idx += NT) {
        int wp = idx >> 2;
        int c4 = idx & 3;
        int w2 = wp - 4;
        float4 v = make_float4(0.f, 0.f, 0.f, 0.f);
        if ((unsigned)w2 < (unsigned)Ww)
            v = *reinterpret_cast<const float4*>(x2b + (((r << 7) + w2) << 7) + c0 + (c4 << 2));
        *reinterpret_cast<float4*>(Bsd + wp * CPAD + (c4 << 2)) = v;
    }
}

__global__ void __launch_bounds__(NT, 1)
cost_volume_kernel(const float* __restrict__ x1,
                   const float* __restrict__ x2,
                   float* __restrict__ out) {
    extern __shared__ float sm[];
    float* As  = sm;                              // [4][128][20]
    float* Bs0 = sm + AS_FLOATS;                  // [136][20] ping
    float* Bs1 = Bs0 + BS_FLOATS;                 // [136][20] pong
    float* Co  = sm + AS_FLOATS + 2 * BS_FLOATS;  // [4][128][81]

    const int tid  = threadIdx.x;
    const int w    = tid & 127;
    const int toff = (tid >> 7) * NJ;             // 0, 3, 6
    const int bblk = blockIdx.x >> 5;
    const int h0   = (blockIdx.x & 31) << 2;
    const float invH = 1.0f / 128.0f;

    const float* x1b  = x1 + ((size_t)(bblk * Hh + h0)) * (Ww * Cc);
    const float* x2b  = x2 + ((size_t)bblk) * (Hh * Ww * Cc);
    float*       outb = out + ((size_t)(bblk * Hh + h0)) * (Ww * OC);

    // Zero the output accumulator band
    for (int idx = tid; idx < CO_FLOATS; idx += NT) Co[idx] = 0.0f;

    for (int cc = 0; cc < NCC; cc++) {
        const int c0 = cc << 4;
        __syncthreads();  // prev chunk's compute done reading As/Bs (covers Co zero at cc=0)

        // Stage x1 band chunk: 2048 float4s, coalesced
        for (int idx = tid; idx < RROWS * Ww * (CCH / 4); idx += NT) {
            int row = idx >> 9;
            int rem = idx & 511;
            int ww  = rem >> 2;
            int c4  = rem & 3;
            float4 v = *reinterpret_cast<const float4*>(
                x1b + (((row << 7) + ww) << 7) + c0 + (c4 << 2));
            *reinterpret_cast<float4*>(As + (row * Ww + ww) * CPAD + (c4 << 2)) = v;
        }
        // Stage first x2 row into ping buffer
        {
            int r0 = h0 - 4;
            if ((unsigned)r0 < (unsigned)Hh) stage_b(x2b, Bs0, r0, c0, tid);
        }

        for (int rr = 0; rr < 12; rr++) {
            __syncthreads();  // Bs[rr&1] staged; round rr-1 consumers done

            // Prefetch next row into the other buffer (overlaps GMEM latency with compute)
            if (rr < 11) {
                int rn = h0 - 4 + rr + 1;
                if ((unsigned)rn < (unsigned)Hh)
                    stage_b(x2b, (rr & 1) ? Bs0 : Bs1, rn, c0, tid);
            }

            const int r = h0 - 4 + rr;
            if ((unsigned)r < (unsigned)Hh) {
                const float* Bcur = (rr & 1) ? Bs1 : Bs0;
                const int row_lo = (rr - 8 > 0) ? rr - 8 : 0;
                const int row_hi = (rr < 3) ? rr : 3;
                if (row_lo == 0 && row_hi == 3)
                    compute_acc<1>(As, Bcur, Co, w, toff, rr, 0, 3);
                else
                    compute_acc<0>(As, Bcur, Co, w, toff, rr, row_lo, row_hi);
            }
        }
    }

    __syncthreads();
    // Single fully-coalesced writeout: Co layout == out layout for this band
    for (int idx = tid; idx < CO_FLOATS; idx += NT)
        outb[idx] = Co[idx] * invH;
}

extern "C" void kernel_launch(void* const* d_in, const int* in_sizes, int n_in,
                              void* d_out, int out_size) {
    const float* x1 = (const float*)d_in[0];
    const float* x2 = (const float*)d_in[1];
    float* out = (float*)d_out;

    static bool attr_set = false;
    if (!attr_set) {
        cudaFuncSetAttribute(cost_volume_kernel,
                             cudaFuncAttributeMaxDynamicSharedMemorySize, SMEM_BYTES);
        attr_set = true;
    }

    dim3 grid(Bb * (Hh / RROWS));  // 256 blocks
    cost_volume_kernel<<<grid, NT, SMEM_BYTES>>>(x1, x2, out);
}

// round 6
// speedup vs baseline: 1.8943x; 1.3018x over previous
#include <cuda_runtime.h>
#include <cuda_bf16.h>

// Cost volume: out[b,h,w,(9i+jj)%81] = (1/H) * sum_c x1[b,h,w,c] * x2[b,h-i,w-jj,c]
// B=8, H=W=C=128, sr=4, D=9, OC=81. Zero padding outside.
//
// Block = (b, band of 2 output rows), 384 threads = 128 w-lanes x 3 slot-groups (3 slots).
// ALL 128 channels resident: As = x1 band (2 rows, full C), Bs = one x2 row (full C).
// 10 rounds (x2 rows h0-4..h0+5); per round each thread register-accumulates 6 complete
// dot products (2 rows x 3 slots) over c=128 with packed fma.rn.f32x2 — no SMEM RMW.
// Outputs staged via Cs and streamed to GMEM write-once, coalesced; flush of round rr-1
// overlaps GMEM staging of round rr. Slot s reads Bs[w+s] = x2[r][w+s-4] => jj = 4 - s.

typedef unsigned long long u64;

#define Bb    8
#define Hh    128
#define Ww    128
#define Cc    128
#define OC    81
#define NT    384
#define NJ    3
#define CPAD  132        // 132 mod 32 = 4 -> LDS.128 lanes cover all 32 banks, conflict-free
#define WB    136        // x2 row width incl. +/-4 halo

#define AS_FLOATS (2 * Ww * CPAD)     // 33792
#define BS_FLOATS (WB * CPAD)         // 17952
#define CS_FLOATS (2 * Ww * 9)        // 2304
#define SMEM_BYTES ((AS_FLOATS + BS_FLOATS + CS_FLOATS) * 4)   // 216192 <= 232448

__device__ __forceinline__ u64 fmax2(u64 a, u64 b, u64 c) {
    u64 d;
    asm("fma.rn.f32x2 %0, %1, %2, %3;" : "=l"(d) : "l"(a), "l"(b), "l"(c));
    return d;
}
__device__ __forceinline__ float hsum_x2(u64 p) {
    float lo, hi;
    asm("mov.b64 {%0, %1}, %2;" : "=f"(lo), "=f"(hi) : "l"(p));
    return lo + hi;
}
__device__ __forceinline__ void f4_to_u64(const float4& v, u64& p0, u64& p1) {
    asm("mov.b64 %0, {%1, %2};" : "=l"(p0) : "f"(v.x), "f"(v.y));
    asm("mov.b64 %0, {%1, %2};" : "=l"(p1) : "f"(v.z), "f"(v.w));
}

// One x2 row's contribution: full-C register accumulation, final values into Cs.
template<int A0, int A1>
__device__ __forceinline__ void compute_round(const float* __restrict__ As,
                                              const float* __restrict__ Bs,
                                              float* __restrict__ Cs,
                                              int w, int toff, float scale) {
    u64 acc[2][NJ];
#pragma unroll
    for (int rw = 0; rw < 2; rw++)
#pragma unroll
        for (int t = 0; t < NJ; t++) acc[rw][t] = 0ull;

    const float4* B0 = reinterpret_cast<const float4*>(Bs + (w + toff) * CPAD);
    const float4* B1 = reinterpret_cast<const float4*>(Bs + (w + toff + 1) * CPAD);
    const float4* B2 = reinterpret_cast<const float4*>(Bs + (w + toff + 2) * CPAD);
    const float4* A0p = reinterpret_cast<const float4*>(As + w * CPAD);
    const float4* A1p = reinterpret_cast<const float4*>(As + (Ww + w) * CPAD);

#pragma unroll
    for (int c4 = 0; c4 < Cc / 4; c4++) {
        u64 b[NJ][2];
        { float4 v = B0[c4]; f4_to_u64(v, b[0][0], b[0][1]); }
        { float4 v = B1[c4]; f4_to_u64(v, b[1][0], b[1][1]); }
        { float4 v = B2[c4]; f4_to_u64(v, b[2][0], b[2][1]); }
        if (A0) {
            u64 a0, a1; float4 v = A0p[c4]; f4_to_u64(v, a0, a1);
#pragma unroll
            for (int t = 0; t < NJ; t++) {
                acc[0][t] = fmax2(a0, b[t][0], acc[0][t]);
                acc[0][t] = fmax2(a1, b[t][1], acc[0][t]);
            }
        }
        if (A1) {
            u64 a0, a1; float4 v = A1p[c4]; f4_to_u64(v, a0, a1);
#pragma unroll
            for (int t = 0; t < NJ; t++) {
                acc[1][t] = fmax2(a0, b[t][0], acc[1][t]);
                acc[1][t] = fmax2(a1, b[t][1], acc[1][t]);
            }
        }
    }
#pragma unroll
    for (int rw = 0; rw < 2; rw++) {
        if ((rw == 0 && A0) || (rw == 1 && A1)) {
#pragma unroll
            for (int t = 0; t < NJ; t++)
                Cs[(rw * Ww + w) * 9 + toff + t] = hsum_x2(acc[rw][t]) * scale;
        }
    }
}

__device__ __forceinline__ void stage_b(const float* __restrict__ x2b,
                                        float* __restrict__ Bs, int r, int tid) {
    // x2 row r, full C, +/-4 halo zero-filled. 4352 float4, coalesced LDG.
    for (int idx = tid; idx < WB * (Cc / 4); idx += NT) {
        int wp = idx >> 5;
        int c4 = idx & 31;
        int w2 = wp - 4;
        float4 v = make_float4(0.f, 0.f, 0.f, 0.f);
        if ((unsigned)w2 < (unsigned)Ww)
            v = *reinterpret_cast<const float4*>(x2b + (((r << 7) + w2) << 7) + (c4 << 2));
        *reinterpret_cast<float4*>(Bs + wp * CPAD + (c4 << 2)) = v;
    }
}

__device__ __forceinline__ void flush_cs(const float* __restrict__ Cs,
                                         float* __restrict__ outb,
                                         int rr, int tid) {
    const int row_lo = (rr >= 1) ? ((rr <= 8) ? 0 : 1) : 0;   // rr==9 -> only rw=1
    const int row_hi = (rr <= 8) ? 1 : 1;
    const int lo = (rr == 9) ? 1 : 0;
    const int hi = (rr == 0) ? 0 : 1;
    (void)row_lo; (void)row_hi;
    const int nact = hi - lo + 1;
    const int total = nact * Ww * 9;
    for (int idx = tid; idx < total; idx += NT) {
        int rowl = idx / (Ww * 9);
        int rem  = idx - rowl * (Ww * 9);
        int ww   = rem / 9;
        int s    = rem - ww * 9;
        int rw   = lo + rowl;
        int oc   = 9 * (rw + 4 - rr) + (4 - s);   // i = h - r, jj = 4 - s
        if (oc < 0) oc += OC;
        outb[(size_t)(rw * Ww + ww) * OC + oc] = Cs[(rw * Ww + ww) * 9 + s];
    }
}

__global__ void __launch_bounds__(NT, 1)
cost_volume_kernel(const float* __restrict__ x1,
                   const float* __restrict__ x2,
                   float* __restrict__ out) {
    extern __shared__ float sm[];
    float* As = sm;                          // [2][128][132]
    float* Bs = sm + AS_FLOATS;              // [136][132]
    float* Cs = sm + AS_FLOATS + BS_FLOATS;  // [2][128][9]

    const int tid  = threadIdx.x;
    const int w    = tid & 127;
    const int toff = (tid >> 7) * NJ;        // 0, 3, 6
    const int bblk = blockIdx.x >> 6;
    const int h0   = (blockIdx.x & 63) << 1;
    const float invH = 1.0f / 128.0f;

    const float* x1b  = x1 + ((size_t)(bblk * Hh + h0)) * (Ww * Cc);
    const float* x2b  = x2 + ((size_t)bblk) * (Hh * Ww * Cc);
    float*       outb = out + ((size_t)(bblk * Hh + h0)) * (Ww * OC);

    // Edge bands: some (rw, i) channels have no valid x2 row -> pre-zero the band.
    if (h0 < 4 || h0 > 122) {
        for (int idx = tid; idx < 2 * Ww * OC; idx += NT) outb[idx] = 0.0f;
    }

    // Stage x1 band, full C: 8192 float4, coalesced.
    for (int idx = tid; idx < 2 * Ww * (Cc / 4); idx += NT) {
        int row = idx >> 12;
        int rem = idx & 4095;
        int ww  = rem >> 5;
        int c4  = rem & 31;
        float4 v = *reinterpret_cast<const float4*>(
            x1b + (((row << 7) + ww) << 7) + (c4 << 2));
        *reinterpret_cast<float4*>(As + (row * Ww + ww) * CPAD + (c4 << 2)) = v;
    }

    int pend_rr = -1;
    for (int rr = 0; rr < 10; rr++) {
        const int r = h0 - 4 + rr;
        const bool rvalid = ((unsigned)r < (unsigned)Hh);

        __syncthreads();  // compute(rr-1) done reading Bs / writing Cs

        if (rvalid) stage_b(x2b, Bs, r, tid);          // GMEM latency overlapped by flush
        if (pend_rr >= 0) flush_cs(Cs, outb, pend_rr, tid);

        __syncthreads();  // Bs staged; Cs flushed

        if (rvalid) {
            if (rr == 0)      compute_round<1, 0>(As, Bs, Cs, w, toff, invH);
            else if (rr == 9) compute_round<0, 1>(As, Bs, Cs, w, toff, invH);
            else              compute_round<1, 1>(As, Bs, Cs, w, toff, invH);
            pend_rr = rr;
        } else {
            pend_rr = -1;
        }
    }
    __syncthreads();
    if (pend_rr >= 0) flush_cs(Cs, outb, pend_rr, tid);
}

extern "C" void kernel_launch(void* const* d_in, const int* in_sizes, int n_in,
                              void* d_out, int out_size) {
    const float* x1 = (const float*)d_in[0];
    const float* x2 = (const float*)d_in[1];
    float* out = (float*)d_out;

    static bool attr_set = false;
    if (!attr_set) {
        cudaFuncSetAttribute(cost_volume_kernel,
                             cudaFuncAttributeMaxDynamicSharedMemorySize, SMEM_BYTES);
        attr_set = true;
    }

    dim3 grid(Bb * (Hh / 2));  // 512 blocks
    cost_volume_kernel<<<grid, NT, SMEM_BYTES>>>(x1, x2, out);
}

// round 8
// speedup vs baseline: 2.5907x; 1.3676x over previous
#include <cuda_runtime.h>
#include <cuda_bf16.h>

// Cost volume: out[b,h,w,(9i+jj)%81] = (1/H) * sum_c x1[b,h,w,c] * x2[b,h-i,w-jj,c]
// B=8, H=W=C=128, sr=4, D=9, OC=81. Zero padding outside.
//
// Block = (b, band of 2 output rows). 512 threads = 128 w-lanes x 4 c-groups (32 ch each).
// A (x1 band slice) lives in REGISTERS per thread (2 rows x 32 c = 64 regs), loaded once.
// Per round (10 x2 rows): stage B row full-C into SMEM; each thread computes partial dots
// for ALL 9 slots over its c-slice (packed fma.rn.f32x2); partials land in Ps[4] slab;
// flush (overlapped with next round's B staging) sums the 4 partials and streams to GMEM
// write-once, coalesced. Slot s reads Bs[w+s] = x2[r][w+s-4] => jj = 4 - s.

typedef unsigned long long u64;

#define Bb    8
#define Hh    128
#define Ww    128
#define Cc    128
#define OC    81
#define NT    512
#define BPAD  132        // Bs row stride: 528B (16B-aligned); 132 mod 32 = 4 -> conflict-free
#define APAD  68         // A-staging row stride: 272B (16B-aligned!); 68 mod 32 = 4 -> conflict-free
#define WB    136        // x2 row width incl. +/-4 halo

#define BS_FLOATS (WB * BPAD)          // 17952 (>= A-stage: 2*128*68 = 17408)
#define PS_FLOATS (4 * 2 * Ww * 9)     // 9216
#define SMEM_BYTES ((BS_FLOATS + PS_FLOATS) * 4)   // 108672 B

__device__ __forceinline__ u64 fmax2(u64 a, u64 b, u64 c) {
    u64 d;
    asm("fma.rn.f32x2 %0, %1, %2, %3;" : "=l"(d) : "l"(a), "l"(b), "l"(c));
    return d;
}
__device__ __forceinline__ float hsum_x2(u64 p) {
    float lo, hi;
    asm("mov.b64 {%0, %1}, %2;" : "=f"(lo), "=f"(hi) : "l"(p));
    return lo + hi;
}
__device__ __forceinline__ void f4_to_u64(const float4& v, u64& p0, u64& p1) {
    asm("mov.b64 %0, {%1, %2};" : "=l"(p0) : "f"(v.x), "f"(v.y));
    asm("mov.b64 %0, {%1, %2};" : "=l"(p1) : "f"(v.z), "f"(v.w));
}

__device__ __forceinline__ void stage_b(const float* __restrict__ x2b,
                                        float* __restrict__ Bs, int r, int tid) {
    // x2 row r, full C, +/-4 halo zero-filled. 4352 float4, coalesced LDG.
    for (int idx = tid; idx < WB * (Cc / 4); idx += NT) {
        int wp = idx >> 5;
        int c4 = idx & 31;
        int w2 = wp - 4;
        float4 v = make_float4(0.f, 0.f, 0.f, 0.f);
        if ((unsigned)w2 < (unsigned)Ww)
            v = *reinterpret_cast<const float4*>(x2b + (((r << 7) + w2) << 7) + (c4 << 2));
        *reinterpret_cast<float4*>(Bs + wp * BPAD + (c4 << 2)) = v;
    }
}

// Sum 4 c-group partials, scale, write final outputs for round rr.
__device__ __forceinline__ void flush_ps(const float* __restrict__ Ps,
                                         float* __restrict__ outb,
                                         int rr, int tid, float invH) {
    const int lo = (rr == 9) ? 1 : 0;
    const int hi = (rr == 0) ? 0 : 1;
    const int total = (hi - lo + 1) * Ww * 9;
    for (int idx = tid; idx < total; idx += NT) {
        int rowl = idx / (Ww * 9);
        int rem  = idx - rowl * (Ww * 9);
        int ww   = rem / 9;
        int s    = rem - ww * 9;
        int rw   = lo + rowl;
        int off  = (rw * Ww + ww) * 9 + s;
        float v = Ps[off] + Ps[2304 + off] + Ps[2 * 2304 + off] + Ps[3 * 2304 + off];
        int oc = 9 * (rw + 4 - rr) + (4 - s);   // i = h - r, jj = 4 - s
        if (oc < 0) oc += OC;
        outb[(size_t)(rw * Ww + ww) * OC + oc] = v * invH;
    }
}

__global__ void __launch_bounds__(NT, 1)
cost_volume_kernel(const float* __restrict__ x1,
                   const float* __restrict__ x2,
                   float* __restrict__ out) {
    extern __shared__ float sm[];
    float* Bs = sm;                 // [136][132]; also reused as A staging buffer at init
    float* Ps = sm + BS_FLOATS;     // [4][2][128][9] partials per c-group

    const int tid  = threadIdx.x;
    const int w    = tid & 127;
    const int cg   = tid >> 7;               // c-group 0..3, owns c in [32*cg, 32*cg+32)
    const int bblk = blockIdx.x >> 6;
    const int h0   = (blockIdx.x & 63) << 1;
    const float invH = 1.0f / 128.0f;

    const float* x1b  = x1 + ((size_t)(bblk * Hh + h0)) * (Ww * Cc);
    const float* x2b  = x2 + ((size_t)bblk) * (Hh * Ww * Cc);
    float*       outb = out + ((size_t)(bblk * Hh + h0)) * (Ww * OC);

    // Edge bands: some (rw, i) channels have no valid x2 row -> pre-zero the band.
    if (h0 < 4 || h0 > 122) {
        for (int idx = tid; idx < 2 * Ww * OC; idx += NT) outb[idx] = 0.0f;
    }

    // ---- Load A into registers: a[rw][16] u64 = 2 rows x 32 c, via 2 staged c-halves ----
    u64 a[2][16];
#pragma unroll
    for (int hc = 0; hc < 2; hc++) {
        // Stage x1 band c-half into Bs region: 2*128*16 float4, coalesced.
        for (int idx = tid; idx < 2 * Ww * 16; idx += NT) {
            int row = idx >> 11;
            int rem = idx & 2047;
            int ww  = rem >> 4;
            int c4  = rem & 15;
            float4 v = *reinterpret_cast<const float4*>(
                x1b + (((row << 7) + ww) << 7) + (hc << 6) + (c4 << 2));
            *reinterpret_cast<float4*>(Bs + (row * Ww + ww) * APAD + (c4 << 2)) = v;
        }
        __syncthreads();
        if ((cg >> 1) == hc) {
            const int cl = (cg & 1) << 5;   // c offset within half (0 or 32)
#pragma unroll
            for (int rw = 0; rw < 2; rw++) {
#pragma unroll
                for (int k = 0; k < 8; k++) {
                    float4 v = *reinterpret_cast<const float4*>(
                        Bs + (rw * Ww + w) * APAD + cl + (k << 2));
                    f4_to_u64(v, a[rw][2 * k], a[rw][2 * k + 1]);
                }
            }
        }
        __syncthreads();
    }

    // ---- Main loop over 10 x2 rows ----
    const float* Bbase = Bs + w * BPAD + (cg << 5);
    int pend = -1;
    for (int rr = 0; rr < 10; rr++) {
        const int r = h0 - 4 + rr;
        const bool rvalid = ((unsigned)r < (unsigned)Hh);

        __syncthreads();  // compute(rr-1) done reading Bs / writing Ps

        if (rvalid) stage_b(x2b, Bs, r, tid);            // GMEM latency overlapped by flush
        if (pend >= 0) flush_ps(Ps, outb, pend, tid, invH);

        __syncthreads();  // Bs staged; Ps consumed

        if (rvalid) {
            u64 acc[2][9];
#pragma unroll
            for (int rw = 0; rw < 2; rw++)
#pragma unroll
                for (int s = 0; s < 9; s++) acc[rw][s] = 0ull;

#pragma unroll
            for (int k = 0; k < 8; k++) {
#pragma unroll
                for (int s = 0; s < 9; s++) {
                    float4 v = *reinterpret_cast<const float4*>(Bbase + s * BPAD + (k << 2));
                    u64 b0, b1;
                    f4_to_u64(v, b0, b1);
                    acc[0][s] = fmax2(a[0][2 * k],     b0, acc[0][s]);
                    acc[0][s] = fmax2(a[0][2 * k + 1], b1, acc[0][s]);
                    acc[1][s] = fmax2(a[1][2 * k],     b0, acc[1][s]);
                    acc[1][s] = fmax2(a[1][2 * k + 1], b1, acc[1][s]);
                }
            }
            // Write partials: Ps[cg][(rw*128+w)*9+s]; lane stride 9 (coprime 32) conflict-free
            float* Pmy = Ps + cg * 2304;
#pragma unroll
            for (int rw = 0; rw < 2; rw++)
#pragma unroll
                for (int s = 0; s < 9; s++)
                    Pmy[(rw * Ww + w) * 9 + s] = hsum_x2(acc[rw][s]);
            pend = rr;
        } else {
            pend = -1;
        }
    }
    __syncthreads();
    if (pend >= 0) flush_ps(Ps, outb, pend, tid, invH);
}

extern "C" void kernel_launch(void* const* d_in, const int* in_sizes, int n_in,
                              void* d_out, int out_size) {
    const float* x1 = (const float*)d_in[0];
    const float* x2 = (const float*)d_in[1];
    float* out = (float*)d_out;

    static bool attr_set = false;
    if (!attr_set) {
        cudaFuncSetAttribute(cost_volume_kernel,
                             cudaFuncAttributeMaxDynamicSharedMemorySize, SMEM_BYTES);
        attr_set = true;
    }

    dim3 grid(Bb * (Hh / 2));  // 512 blocks
    cost_volume_kernel<<<grid, NT, SMEM_BYTES>>>(x1, x2, out);
}